// round 8
// baseline (speedup 1.0000x reference)
#include <cuda_runtime.h>
#include <cuda_fp16.h>
#include <cstdint>
#include <math.h>

// ---------------- problem constants ----------------
#define NA 50000
#define NP 50000
#define EDG 400000
#define KH 8
#define DH 32
#define KD 256
#define SLOPE 0.2f

// GEMM tiling: block 128(M) x 256(N), 8 warps (2m x 4n), warp tile 64x64, BK=16
// fp16 operands packed as k-pairs (uint32 = 2 halves along k)
#define BM 128
#define BK 16
#define NKT (KD / BK)      // 16
#define LDA 12             // A smem stride in u32 ([m:128][kpair:8] + pad)
#define LDBN 264           // B smem stride in u32 ([kpair:8][n:256] + pad)
#define ASZ (128 * LDA)    // 1536 u32
#define BSZ (8 * LDBN)     // 2112 u32
#define SMEM_BYTES ((2 * ASZ + 2 * BSZ) * 4)   // 29184

#define NBLK 196           // ceil(50000/256)

// ---------------- device scratch ----------------
__device__ float g_PA[NA * KD];
__device__ float g_PP[NP * KD];

__device__ float g_elA_aA[NA * KH];
__device__ float g_erP_aA[NP * KH];
__device__ float g_elP_aP[NP * KH];
__device__ float g_erA_aP[NA * KH];
__device__ float g_erP_aP[NP * KH];

__device__ float g_ft_w[NP * KD];
__device__ float g_ft_wb[NA * KD];
__device__ float g_ft_c[NP * KD];

__device__ float g_rf_w[NP * KD];
__device__ float g_rf_c[NP * KD];
__device__ float g_nodeP[NP * KD];

// CSR scratch, one set per relation
__device__ int g_counts[3][50000];
__device__ int g_cursor[3][50000];
__device__ int g_offsets[3][50001];
__device__ int g_partials[3][NBLK + 1];
__device__ int g_ssort[3][EDG];

// ---------------- helpers ----------------
__device__ __forceinline__ float leaky(float v) {
    return v > 0.f ? v : SLOPE * v;
}
__device__ __forceinline__ uint32_t pack_h2(float lo, float hi) {
    __half2 h = __floats2half2_rn(lo, hi);
    return *(uint32_t*)&h;
}
__device__ __forceinline__ void mma_f16(float c[4], uint32_t a0, uint32_t a1,
                                        uint32_t a2, uint32_t a3,
                                        uint32_t b0, uint32_t b1) {
    asm volatile(
        "mma.sync.aligned.m16n8k16.row.col.f32.f16.f16.f32 "
        "{%0,%1,%2,%3}, {%4,%5,%6,%7}, {%8,%9}, {%0,%1,%2,%3};"
        : "+f"(c[0]), "+f"(c[1]), "+f"(c[2]), "+f"(c[3])
        : "r"(a0), "r"(a1), "r"(a2), "r"(a3), "r"(b0), "r"(b1));
}

struct GemmJob {
    const float* A;
    const float* B;
    float*       C;
    const float* bias;
    const float* gate;
    const float* av0; float* ao0;
    const float* av1; float* ao1;
    const float* av2; float* ao2;
};

// ---------------- multi-job fp16 tensor-core GEMM ----------------
// per job: C[M,256] = A[M,256] @ B[256,256], fp32 accumulate
__global__ void __launch_bounds__(256, 1) gemm_multi(
    GemmJob j0, GemmJob j1, GemmJob j2, int nb, int M)
{
    extern __shared__ uint32_t smem[];
    const int tid = threadIdx.x;
    const int lane = tid & 31;
    const int wid = tid >> 5;
    const int wm = (wid & 1) * 64;
    const int wn = (wid >> 1) * 64;
    const int m0 = blockIdx.x * BM;

    const int qr = lane >> 2;   // 0..7
    const int qc = lane & 3;    // 0..3

    // global->smem assignments
    const int am = tid >> 1;           // A row 0..127
    const int aq = (tid & 1) * 8;      // A k offset 0 or 8
    const int bp2 = tid >> 5;          // B k-pair 0..7 (k rows 2p, 2p+1)
    const int bn0 = (tid & 31) * 8;    // B n offset 0..248

    float4 rA[2], rB[4];

    auto g_load = [&](int kt, const float* __restrict__ A, const float* __restrict__ B) {
        const int k0 = kt * BK;
        int row = m0 + am;
        if (row < M) {
            rA[0] = *(const float4*)&A[(size_t)row * KD + k0 + aq];
            rA[1] = *(const float4*)&A[(size_t)row * KD + k0 + aq + 4];
        } else {
            rA[0] = make_float4(0.f, 0.f, 0.f, 0.f);
            rA[1] = rA[0];
        }
        const float* b0p = &B[(size_t)(k0 + 2 * bp2) * KD + bn0];
        const float* b1p = b0p + KD;
        rB[0] = *(const float4*)&b0p[0];
        rB[1] = *(const float4*)&b0p[4];
        rB[2] = *(const float4*)&b1p[0];
        rB[3] = *(const float4*)&b1p[4];
    };
    auto s_store = [&](int buf) {
        // A: pack adjacent k into u32 pairs -> As[m][kpair]
        uint32_t* as = &smem[buf * ASZ + am * LDA + (aq >> 1)];
        uint4 va;
        va.x = pack_h2(rA[0].x, rA[0].y);
        va.y = pack_h2(rA[0].z, rA[0].w);
        va.z = pack_h2(rA[1].x, rA[1].y);
        va.w = pack_h2(rA[1].z, rA[1].w);
        *(uint4*)as = va;
        // B: pack (k=2p, k=2p+1) vertically -> Bs[kpair][n]
        uint32_t* bs = &smem[2 * ASZ + buf * BSZ + bp2 * LDBN + bn0];
        const float* r0 = (const float*)&rB[0];
        const float* r1 = (const float*)&rB[2];
        uint4 w0, w1;
        w0.x = pack_h2(r0[0], r1[0]);
        w0.y = pack_h2(r0[1], r1[1]);
        w0.z = pack_h2(r0[2], r1[2]);
        w0.w = pack_h2(r0[3], r1[3]);
        w1.x = pack_h2(r0[4], r1[4]);
        w1.y = pack_h2(r0[5], r1[5]);
        w1.z = pack_h2(r0[6], r1[6]);
        w1.w = pack_h2(r0[7], r1[7]);
        *(uint4*)&bs[0] = w0;
        *(uint4*)&bs[4] = w1;
    };

#pragma unroll
    for (int o = 0; o < 3; o++) {
        if (o >= nb) break;
        const GemmJob J = (o == 0) ? j0 : (o == 1) ? j1 : j2;

        float acc[4][8][4];
#pragma unroll
        for (int mi = 0; mi < 4; mi++)
#pragma unroll
            for (int ni = 0; ni < 8; ni++)
#pragma unroll
                for (int r = 0; r < 4; r++) acc[mi][ni][r] = 0.f;

        g_load(0, J.A, J.B);
        s_store(0);
        __syncthreads();

        for (int kt = 0; kt < NKT; kt++) {
            const int cur = kt & 1;
            if (kt + 1 < NKT) g_load(kt + 1, J.A, J.B);

            const uint32_t* asb = &smem[cur * ASZ];
            const uint32_t* bsb = &smem[2 * ASZ + cur * BSZ];
            uint32_t a[4][4], b[8][2];
#pragma unroll
            for (int mi = 0; mi < 4; mi++) {
                int r0 = wm + mi * 16 + qr;
                a[mi][0] = asb[r0 * LDA + qc];
                a[mi][1] = asb[(r0 + 8) * LDA + qc];
                a[mi][2] = asb[r0 * LDA + qc + 4];
                a[mi][3] = asb[(r0 + 8) * LDA + qc + 4];
            }
#pragma unroll
            for (int ni = 0; ni < 8; ni++) {
                int c0 = wn + ni * 8 + qr;
                b[ni][0] = bsb[qc * LDBN + c0];
                b[ni][1] = bsb[(qc + 4) * LDBN + c0];
            }
#pragma unroll
            for (int mi = 0; mi < 4; mi++)
#pragma unroll
                for (int ni = 0; ni < 8; ni++)
                    mma_f16(acc[mi][ni], a[mi][0], a[mi][1], a[mi][2], a[mi][3],
                            b[ni][0], b[ni][1]);

            if (kt + 1 < NKT) {
                s_store(1 - cur);
                __syncthreads();
            }
        }

        // ---- fused attention dots (micro jobs) ----
        if (J.av0) {
            const float* avs[3] = { J.av0, J.av1, J.av2 };
            float*       aos[3] = { J.ao0, J.ao1, J.ao2 };
            const int h0 = wn >> 5;
#pragma unroll
            for (int t = 0; t < 3; t++) {
                const float* av = avs[t];
                if (!av) break;
                float* ao = aos[t];
                float c0[8], c1[8];
#pragma unroll
                for (int ni = 0; ni < 8; ni++) {
                    int col = wn + ni * 8 + qc * 2;
                    int idx = (col >> 5) * 64 + (col & 31);
                    c0[ni] = av[idx];
                    c1[ni] = av[idx + 1];
                }
#pragma unroll
                for (int mi = 0; mi < 4; mi++) {
#pragma unroll
                    for (int half = 0; half < 2; half++) {
                        float pa = 0.f, pb = 0.f;
#pragma unroll
                        for (int ni = 0; ni < 4; ni++)
                            pa += acc[mi][ni][half * 2] * c0[ni]
                                + acc[mi][ni][half * 2 + 1] * c1[ni];
#pragma unroll
                        for (int ni = 4; ni < 8; ni++)
                            pb += acc[mi][ni][half * 2] * c0[ni]
                                + acc[mi][ni][half * 2 + 1] * c1[ni];
                        pa += __shfl_xor_sync(0xffffffffu, pa, 1);
                        pa += __shfl_xor_sync(0xffffffffu, pa, 2);
                        pb += __shfl_xor_sync(0xffffffffu, pb, 1);
                        pb += __shfl_xor_sync(0xffffffffu, pb, 2);
                        int row = m0 + wm + mi * 16 + qr + half * 8;
                        if (qc == 0 && row < M) {
                            ao[row * KH + h0]     = pa;
                            ao[row * KH + h0 + 1] = pb;
                        }
                    }
                }
            }
        }

        float g = 0.f;
        if (J.gate) g = 1.f / (1.f + __expf(-J.gate[0]));

        // ---- C epilogue ----
#pragma unroll
        for (int mi = 0; mi < 4; mi++) {
#pragma unroll
            for (int half = 0; half < 2; half++) {
                int row = m0 + wm + mi * 16 + qr + half * 8;
                if (row >= M) continue;
                float* dst = &J.C[(size_t)row * KD + wn];
#pragma unroll
                for (int ni = 0; ni < 8; ni++) {
                    int col = ni * 8 + qc * 2;
                    float2 v;
                    v.x = acc[mi][ni][half * 2 + 0];
                    v.y = acc[mi][ni][half * 2 + 1];
                    if (J.bias) {
                        v.x += J.bias[wn + col + 0];
                        v.y += J.bias[wn + col + 1];
                    }
                    if (J.gate) {
                        float2 prev = *(const float2*)&dst[col];
                        v.x = g * v.x + (1.f - g) * prev.x;
                        v.y = g * v.y + (1.f - g) * prev.y;
                    }
                    *(float2*)&dst[col] = v;
                }
            }
        }
        __syncthreads();
    }
}

// ---------------- CSR build ----------------
__global__ void csr_hist(const int* __restrict__ dst, int* __restrict__ counts)
{
    int e = blockIdx.x * blockDim.x + threadIdx.x;
    if (e < EDG) atomicAdd(&counts[dst[e]], 1);
}

__global__ void scan_block(const int* __restrict__ in, int* __restrict__ out,
                           int* __restrict__ partials, int n)
{
    __shared__ int wsum[8];
    int i = blockIdx.x * 256 + threadIdx.x;
    int lane = threadIdx.x & 31, wid = threadIdx.x >> 5;
    int v = (i < n) ? in[i] : 0;
    int x = v;
#pragma unroll
    for (int o = 1; o < 32; o <<= 1) {
        int t = __shfl_up_sync(0xffffffffu, x, o);
        if (lane >= o) x += t;
    }
    if (lane == 31) wsum[wid] = x;
    __syncthreads();
    if (wid == 0) {
        int w = (lane < 8) ? wsum[lane] : 0;
#pragma unroll
        for (int o = 1; o < 8; o <<= 1) {
            int t = __shfl_up_sync(0xffffffffu, w, o);
            if (lane >= o) w += t;
        }
        if (lane < 8) wsum[lane] = w;
    }
    __syncthreads();
    int wpre = (wid > 0) ? wsum[wid - 1] : 0;
    if (i < n) out[i] = wpre + x - v;
    if (threadIdx.x == 0) partials[blockIdx.x] = wsum[7];
}

__global__ void scan_top(int* __restrict__ partials, int nb)
{
    __shared__ int wsum[8];
    int i = threadIdx.x;
    int lane = i & 31, wid = i >> 5;
    int v = (i < nb) ? partials[i] : 0;
    int x = v;
#pragma unroll
    for (int o = 1; o < 32; o <<= 1) {
        int t = __shfl_up_sync(0xffffffffu, x, o);
        if (lane >= o) x += t;
    }
    if (lane == 31) wsum[wid] = x;
    __syncthreads();
    if (wid == 0) {
        int w = (lane < 8) ? wsum[lane] : 0;
#pragma unroll
        for (int o = 1; o < 8; o <<= 1) {
            int t = __shfl_up_sync(0xffffffffu, w, o);
            if (lane >= o) w += t;
        }
        if (lane < 8) wsum[lane] = w;
    }
    __syncthreads();
    int wpre = (wid > 0) ? wsum[wid - 1] : 0;
    if (i < nb) partials[i] = wpre + x - v;
    if (i == 0) partials[nb] = wsum[7];
}

__global__ void scan_add(int* __restrict__ offsets, const int* __restrict__ partials, int n)
{
    int i = blockIdx.x * 256 + threadIdx.x;
    if (i < n) offsets[i] += partials[blockIdx.x];
    if (i == 0) offsets[n] = partials[gridDim.x];
}

__global__ void csr_scatter(const int* __restrict__ src, const int* __restrict__ dst,
                            const int* __restrict__ offsets, int* __restrict__ cursor,
                            int* __restrict__ ssort)
{
    int e = blockIdx.x * blockDim.x + threadIdx.x;
    if (e >= EDG) return;
    int d = dst[e];
    int pos = offsets[d] + atomicAdd(&cursor[d], 1);
    ssort[pos] = src[e];
}

// ---------------- fused micro gather: softmax + weighted sum + relu ----------------
__global__ void micro_gather(const int* __restrict__ ssort, const int* __restrict__ offsets,
                             const float* __restrict__ el, const float* __restrict__ er,
                             const float* __restrict__ Psrc, float* __restrict__ ft, int n_dst)
{
    int d = (blockIdx.x * blockDim.x + threadIdx.x) >> 5;
    int lane = threadIdx.x & 31;
    if (d >= n_dst) return;
    int beg = offsets[d], end = offsets[d + 1];
    float* dstp = &ft[(size_t)d * KD + lane * 8];
    if (beg == end) {
        float4 z = make_float4(0.f, 0.f, 0.f, 0.f);
        *(float4*)dstp = z;
        *(float4*)(dstp + 4) = z;
        return;
    }
    const int h8 = lane & 7;
    float erh = er[d * KH + h8];

    // pass 1: per-head max, 4 edges/iter
    float mx = -1e30f;
    {
        int sub = lane >> 3;
        for (int i = beg; i < end; i += 4) {
            int e = i + sub;
            if (e < end) {
                int s = ssort[e];
                mx = fmaxf(mx, leaky(el[s * KH + h8] + erh));
            }
        }
        mx = fmaxf(mx, __shfl_xor_sync(0xffffffffu, mx, 8));
        mx = fmaxf(mx, __shfl_xor_sync(0xffffffffu, mx, 16));
    }

    // pass 2: exp + weighted feature accumulation, 2 edges/iter
    const int hk = lane >> 2;
    float acc[8] = {0.f, 0.f, 0.f, 0.f, 0.f, 0.f, 0.f, 0.f};
    float se = 0.f;
    int i = beg;
    for (; i + 2 <= end; i += 2) {
        int s0 = ssort[i], s1 = ssort[i + 1];
        float w0 = 0.f, w1 = 0.f;
        if (lane < KH) {
            w0 = __expf(leaky(el[s0 * KH + lane] + erh) - mx);
            w1 = __expf(leaky(el[s1 * KH + lane] + erh) - mx);
            se += w0 + w1;
        }
        float wk0 = __shfl_sync(0xffffffffu, w0, hk);
        float wk1 = __shfl_sync(0xffffffffu, w1, hk);
        const float4* p0 = (const float4*)&Psrc[(size_t)s0 * KD + lane * 8];
        const float4* p1 = (const float4*)&Psrc[(size_t)s1 * KD + lane * 8];
        float4 a0 = p0[0], a1 = p0[1], b0 = p1[0], b1 = p1[1];
        acc[0] = fmaf(wk0, a0.x, acc[0]); acc[0] = fmaf(wk1, b0.x, acc[0]);
        acc[1] = fmaf(wk0, a0.y, acc[1]); acc[1] = fmaf(wk1, b0.y, acc[1]);
        acc[2] = fmaf(wk0, a0.z, acc[2]); acc[2] = fmaf(wk1, b0.z, acc[2]);
        acc[3] = fmaf(wk0, a0.w, acc[3]); acc[3] = fmaf(wk1, b0.w, acc[3]);
        acc[4] = fmaf(wk0, a1.x, acc[4]); acc[4] = fmaf(wk1, b1.x, acc[4]);
        acc[5] = fmaf(wk0, a1.y, acc[5]); acc[5] = fmaf(wk1, b1.y, acc[5]);
        acc[6] = fmaf(wk0, a1.z, acc[6]); acc[6] = fmaf(wk1, b1.z, acc[6]);
        acc[7] = fmaf(wk0, a1.w, acc[7]); acc[7] = fmaf(wk1, b1.w, acc[7]);
    }
    if (i < end) {
        int s0 = ssort[i];
        float w0 = 0.f;
        if (lane < KH) {
            w0 = __expf(leaky(el[s0 * KH + lane] + erh) - mx);
            se += w0;
        }
        float wk0 = __shfl_sync(0xffffffffu, w0, hk);
        const float4* p0 = (const float4*)&Psrc[(size_t)s0 * KD + lane * 8];
        float4 a0 = p0[0], a1 = p0[1];
        acc[0] = fmaf(wk0, a0.x, acc[0]);
        acc[1] = fmaf(wk0, a0.y, acc[1]);
        acc[2] = fmaf(wk0, a0.z, acc[2]);
        acc[3] = fmaf(wk0, a0.w, acc[3]);
        acc[4] = fmaf(wk0, a1.x, acc[4]);
        acc[5] = fmaf(wk0, a1.y, acc[5]);
        acc[6] = fmaf(wk0, a1.z, acc[6]);
        acc[7] = fmaf(wk0, a1.w, acc[7]);
    }
    float inv = 1.f / __shfl_sync(0xffffffffu, se, hk);
    float4 o0, o1;
    o0.x = fmaxf(acc[0] * inv, 0.f);
    o0.y = fmaxf(acc[1] * inv, 0.f);
    o0.z = fmaxf(acc[2] * inv, 0.f);
    o0.w = fmaxf(acc[3] * inv, 0.f);
    o1.x = fmaxf(acc[4] * inv, 0.f);
    o1.y = fmaxf(acc[5] * inv, 0.f);
    o1.z = fmaxf(acc[6] * inv, 0.f);
    o1.w = fmaxf(acc[7] * inv, 0.f);
    *(float4*)dstp = o0;
    *(float4*)(dstp + 4) = o1;
}

// ---------------- final paper ----------------
__global__ void final_paper(const float* __restrict__ rfw, const float* __restrict__ rfc,
                            const float* __restrict__ nodep, const float* __restrict__ attnM,
                            const float* __restrict__ resw, float* __restrict__ out)
{
    int n = blockIdx.x;
    int k = threadIdx.x >> 5;
    int lane = threadIdx.x & 31;
    size_t idx = (size_t)n * KD + k * DH + lane;
    float np = nodep[idx], rw = rfw[idx], rc = rfc[idx];
    float a1 = attnM[k * 64 + lane];
    float a2 = attnM[k * 64 + 32 + lane];
    float sw = a1 * np + a2 * rw;
    float sc = a1 * np + a2 * rc;
#pragma unroll
    for (int s = 16; s > 0; s >>= 1) {
        sw += __shfl_xor_sync(0xffffffffu, sw, s);
        sc += __shfl_xor_sync(0xffffffffu, sc, s);
    }
    sw = leaky(sw);
    sc = leaky(sc);
    float mx = fmaxf(sw, sc);
    float ew = __expf(sw - mx), ec = __expf(sc - mx);
    float aw = ew / (ew + ec);
    float val = aw * rw + (1.f - aw) * rc;
    float g = 1.f / (1.f + __expf(-resw[0]));
    size_t o = (size_t)NA * KD + idx;
    out[o] = g * val + (1.f - g) * out[o];
}

// ---------------- launch ----------------
extern "C" void kernel_launch(void* const* d_in, const int* in_sizes, int n_in,
                              void* d_out, int out_size)
{
    const float* feats_author    = (const float*)d_in[0];
    const float* feats_paper     = (const float*)d_in[1];
    const float* W_micro_author  = (const float*)d_in[2];
    const float* W_micro_paper   = (const float*)d_in[3];
    const float* attn_micro_a    = (const float*)d_in[4];
    const float* attn_micro_p    = (const float*)d_in[5];
    const float* W_macro_node_p  = (const float*)d_in[7];
    const float* W_rel_writes    = (const float*)d_in[8];
    const float* W_rel_wb        = (const float*)d_in[9];
    const float* W_rel_cites     = (const float*)d_in[10];
    const float* attn_macro      = (const float*)d_in[11];
    const float* W_res_author    = (const float*)d_in[12];
    const float* b_res_author    = (const float*)d_in[13];
    const float* W_res_paper     = (const float*)d_in[14];
    const float* b_res_paper     = (const float*)d_in[15];
    const float* res_w_author    = (const float*)d_in[16];
    const float* res_w_paper     = (const float*)d_in[17];
    const int*   writes_src      = (const int*)d_in[18];
    const int*   writes_dst      = (const int*)d_in[19];
    const int*   wb_src          = (const int*)d_in[20];
    const int*   wb_dst          = (const int*)d_in[21];
    const int*   cites_src       = (const int*)d_in[22];
    const int*   cites_dst       = (const int*)d_in[23];
    float* out = (float*)d_out;

    float *PA, *PP, *elA_aA, *erP_aA, *elP_aP, *erA_aP, *erP_aP;
    float *ft_w, *ft_wb, *ft_c, *rf_w, *rf_c, *nodeP;
    int *counts, *cursor, *offsets, *partials, *ssort;
    cudaGetSymbolAddress((void**)&PA, g_PA);
    cudaGetSymbolAddress((void**)&PP, g_PP);
    cudaGetSymbolAddress((void**)&elA_aA, g_elA_aA);
    cudaGetSymbolAddress((void**)&erP_aA, g_erP_aA);
    cudaGetSymbolAddress((void**)&elP_aP, g_elP_aP);
    cudaGetSymbolAddress((void**)&erA_aP, g_erA_aP);
    cudaGetSymbolAddress((void**)&erP_aP, g_erP_aP);
    cudaGetSymbolAddress((void**)&ft_w, g_ft_w);
    cudaGetSymbolAddress((void**)&ft_wb, g_ft_wb);
    cudaGetSymbolAddress((void**)&ft_c, g_ft_c);
    cudaGetSymbolAddress((void**)&rf_w, g_rf_w);
    cudaGetSymbolAddress((void**)&rf_c, g_rf_c);
    cudaGetSymbolAddress((void**)&nodeP, g_nodeP);
    cudaGetSymbolAddress((void**)&counts, g_counts);
    cudaGetSymbolAddress((void**)&cursor, g_cursor);
    cudaGetSymbolAddress((void**)&offsets, g_offsets);
    cudaGetSymbolAddress((void**)&partials, g_partials);
    cudaGetSymbolAddress((void**)&ssort, g_ssort);

    static cudaStream_t s2 = nullptr;
    static cudaEvent_t evFork = nullptr, evMicro = nullptr, evG[3] = {};
    if (!s2) {
        cudaStreamCreateWithFlags(&s2, cudaStreamNonBlocking);
        cudaEventCreateWithFlags(&evFork, cudaEventDisableTiming);
        cudaEventCreateWithFlags(&evMicro, cudaEventDisableTiming);
        for (int r = 0; r < 3; r++)
            cudaEventCreateWithFlags(&evG[r], cudaEventDisableTiming);
    }

    cudaFuncSetAttribute(gemm_multi, cudaFuncAttributeMaxDynamicSharedMemorySize, SMEM_BYTES);

    const int GG = (NA + BM - 1) / BM;          // 391
    const int EB = (EDG + 255) / 256;
    const int GB = (NA * 32 + 255) / 256;

    GemmJob jz = {};

    struct Rel { const int* src; const int* dst; const float* el; const float* er;
                 const float* P; float* ft; int n; };
    Rel rels[3] = {
        { writes_src, writes_dst, elA_aA, erP_aA, PA, ft_w,  NP },
        { wb_src,     wb_dst,     elP_aP, erA_aP, PP, ft_wb, NA },
        { cites_src,  cites_dst,  elP_aP, erP_aP, PP, ft_c,  NP },
    };

    // ---- fork side stream for CSR builds ----
    cudaEventRecord(evFork, 0);
    cudaStreamWaitEvent(s2, evFork, 0);
    for (int r = 0; r < 3; r++) {
        Rel& R = rels[r];
        int* cnt = counts  + r * 50000;
        int* cur = cursor  + r * 50000;
        int* off = offsets + r * 50001;
        int* par = partials + r * (NBLK + 1);
        int* srt = ssort   + r * EDG;
        cudaMemsetAsync(cnt, 0, R.n * sizeof(int), s2);
        cudaMemsetAsync(cur, 0, R.n * sizeof(int), s2);
        csr_hist<<<EB, 256, 0, s2>>>(R.dst, cnt);
        scan_block<<<NBLK, 256, 0, s2>>>(cnt, off, par, R.n);
        scan_top<<<1, 256, 0, s2>>>(par, NBLK);
        scan_add<<<NBLK, 256, 0, s2>>>(off, par, R.n);
        csr_scatter<<<EB, 256, 0, s2>>>(R.src, R.dst, off, cur, srt);
    }

    // ---- main stream: micro projections (with fused attn dots) ----
    {
        GemmJob ja = { feats_author, W_micro_author, PA, nullptr, nullptr,
                       attn_micro_a + 0,  elA_aA,
                       attn_micro_p + 32, erA_aP,
                       nullptr, nullptr };
        gemm_multi<<<GG, 256, SMEM_BYTES>>>(ja, jz, jz, 1, NA);
    }
    {
        GemmJob ja = { feats_paper, W_micro_paper, PP, nullptr, nullptr,
                       attn_micro_a + 32, erP_aA,
                       attn_micro_p + 0,  elP_aP,
                       attn_micro_p + 32, erP_aP };
        gemm_multi<<<GG, 256, SMEM_BYTES>>>(ja, jz, jz, 1, NP);
    }
    cudaEventRecord(evMicro, 0);

    // ---- side stream: gathers ----
    cudaStreamWaitEvent(s2, evMicro, 0);
    for (int r = 0; r < 3; r++) {
        Rel& R = rels[r];
        int* off = offsets + r * 50001;
        int* srt = ssort   + r * EDG;
        micro_gather<<<GB, 256, 0, s2>>>(srt, off, R.el, R.er, R.P, R.ft, R.n);
        cudaEventRecord(evG[r], s2);
    }

    // ---- main stream: independent GEMMs overlap with gathers ----
    {
        GemmJob ja = { feats_author, W_res_author, out, b_res_author, nullptr,
                       nullptr, nullptr, nullptr, nullptr, nullptr, nullptr };
        GemmJob jb = { feats_paper, W_macro_node_p, nodeP, nullptr, nullptr,
                       nullptr, nullptr, nullptr, nullptr, nullptr, nullptr };
        GemmJob jc = { feats_paper, W_res_paper, out + (size_t)NA * KD, b_res_paper, nullptr,
                       nullptr, nullptr, nullptr, nullptr, nullptr, nullptr };
        gemm_multi<<<GG, 256, SMEM_BYTES>>>(ja, jb, jc, 3, NA);
    }

    // ---- macro projections, each gated on its gather ----
    cudaStreamWaitEvent(0, evG[0], 0);
    {
        GemmJob ja = { ft_w, W_rel_writes, rf_w, nullptr, nullptr,
                       nullptr, nullptr, nullptr, nullptr, nullptr, nullptr };
        gemm_multi<<<GG, 256, SMEM_BYTES>>>(ja, jz, jz, 1, NP);
    }
    cudaStreamWaitEvent(0, evG[2], 0);
    {
        GemmJob ja = { ft_c, W_rel_cites, rf_c, nullptr, nullptr,
                       nullptr, nullptr, nullptr, nullptr, nullptr, nullptr };
        gemm_multi<<<GG, 256, SMEM_BYTES>>>(ja, jz, jz, 1, NP);
    }
    cudaStreamWaitEvent(0, evG[1], 0);
    {
        GemmJob ja = { ft_wb, W_rel_wb, out, nullptr, res_w_author,
                       nullptr, nullptr, nullptr, nullptr, nullptr, nullptr };
        gemm_multi<<<GG, 256, SMEM_BYTES>>>(ja, jz, jz, 1, NA);
    }

    // ---- final paper fusion ----
    final_paper<<<NP, 256>>>(rf_w, rf_c, nodeP, attn_macro, res_w_paper, out);
}

// round 9
// speedup vs baseline: 1.1211x; 1.1211x over previous
#include <cuda_runtime.h>
#include <cstdint>
#include <math.h>

// ---------------- problem constants ----------------
#define NA 50000
#define NP 50000
#define EDG 400000
#define KH 8
#define DH 32
#define KD 256
#define SLOPE 0.2f

// GEMM tiling: block 128(M) x 256(N), 8 warps (2m x 4n), warp tile 64x64, BK=16 (tf32)
#define BM 128
#define BK 16
#define NKT (KD / BK)      // 16
#define LDK 20
#define LDBN 264
#define ASZ (128 * LDK)
#define BSZ (BK * LDBN)
#define SMEM_BYTES ((2 * ASZ + 2 * BSZ) * 4)   // 54272

#define NBLK 196           // ceil(50000/256)

// ---------------- device scratch ----------------
__device__ float g_PA[NA * KD];
__device__ float g_PP[NP * KD];

__device__ float g_elA_aA[NA * KH];
__device__ float g_erP_aA[NP * KH];
__device__ float g_elP_aP[NP * KH];
__device__ float g_erA_aP[NA * KH];
__device__ float g_erP_aP[NP * KH];

__device__ float g_ft_w[NP * KD];
__device__ float g_ft_wb[NA * KD];
__device__ float g_ft_c[NP * KD];

__device__ float g_rf_w[NP * KD];
__device__ float g_rf_c[NP * KD];
__device__ float g_nodeP[NP * KD];

// CSR scratch, one set per relation
__device__ int g_counts[3][50000];
__device__ int g_cursor[3][50000];
__device__ int g_offsets[3][50001];
__device__ int g_partials[3][NBLK + 1];
__device__ int g_ssort[3][EDG];

// ---------------- helpers ----------------
__device__ __forceinline__ float leaky(float v) {
    return v > 0.f ? v : SLOPE * v;
}
__device__ __forceinline__ uint32_t f2tf32(float f) {
    uint32_t r;
    asm("cvt.rna.tf32.f32 %0, %1;" : "=r"(r) : "f"(f));
    return r;
}
__device__ __forceinline__ void mma_tf32(float c[4], uint32_t a0, uint32_t a1,
                                         uint32_t a2, uint32_t a3,
                                         uint32_t b0, uint32_t b1) {
    asm volatile(
        "mma.sync.aligned.m16n8k8.row.col.f32.tf32.tf32.f32 "
        "{%0,%1,%2,%3}, {%4,%5,%6,%7}, {%8,%9}, {%0,%1,%2,%3};"
        : "+f"(c[0]), "+f"(c[1]), "+f"(c[2]), "+f"(c[3])
        : "r"(a0), "r"(a1), "r"(a2), "r"(a3), "r"(b0), "r"(b1));
}

struct GemmJob {
    const float* A;
    const float* B;
    float*       C;
    const float* bias;
    const float* gate;
    const float* av0; float* ao0;
    const float* av1; float* ao1;
    const float* av2; float* ao2;
};

// ---------------- multi-job tf32 GEMM (R7-proven mainloop) ----------------
__global__ void __launch_bounds__(256, 1) gemm_multi(
    GemmJob j0, GemmJob j1, GemmJob j2, int nb, int M)
{
    extern __shared__ uint32_t smem[];
    const int tid = threadIdx.x;
    const int lane = tid & 31;
    const int wid = tid >> 5;
    const int wm = (wid & 1) * 64;
    const int wn = (wid >> 1) * 64;
    const int m0 = blockIdx.x * BM;

    const int qr = lane >> 2;
    const int qc = lane & 3;

    const int am = tid >> 1;
    const int aq = (tid & 1) * 8;
    const int bkr = tid >> 4;
    const int bnc = (tid & 15) * 16;

    float4 rA[2], rB[4];

    auto g_load = [&](int kt, const float* __restrict__ A, const float* __restrict__ B) {
        const int k0 = kt * BK;
        int row = m0 + am;
        if (row < M) {
            rA[0] = *(const float4*)&A[(size_t)row * KD + k0 + aq];
            rA[1] = *(const float4*)&A[(size_t)row * KD + k0 + aq + 4];
        } else {
            rA[0] = make_float4(0.f, 0.f, 0.f, 0.f);
            rA[1] = rA[0];
        }
        const float* bp = &B[(size_t)(k0 + bkr) * KD + bnc];
        rB[0] = *(const float4*)&bp[0];
        rB[1] = *(const float4*)&bp[4];
        rB[2] = *(const float4*)&bp[8];
        rB[3] = *(const float4*)&bp[12];
    };
    auto s_store = [&](int buf) {
        uint32_t* as = &smem[buf * ASZ + am * LDK + aq];
        uint4 v0, v1;
        v0.x = f2tf32(rA[0].x); v0.y = f2tf32(rA[0].y);
        v0.z = f2tf32(rA[0].z); v0.w = f2tf32(rA[0].w);
        v1.x = f2tf32(rA[1].x); v1.y = f2tf32(rA[1].y);
        v1.z = f2tf32(rA[1].z); v1.w = f2tf32(rA[1].w);
        *(uint4*)&as[0] = v0;
        *(uint4*)&as[4] = v1;
        uint32_t* bs = &smem[2 * ASZ + buf * BSZ + bkr * LDBN + bnc];
#pragma unroll
        for (int q = 0; q < 4; q++) {
            uint4 w;
            w.x = f2tf32(((const float*)&rB[q])[0]);
            w.y = f2tf32(((const float*)&rB[q])[1]);
            w.z = f2tf32(((const float*)&rB[q])[2]);
            w.w = f2tf32(((const float*)&rB[q])[3]);
            *(uint4*)&bs[q * 4] = w;
        }
    };

#pragma unroll
    for (int o = 0; o < 3; o++) {
        if (o >= nb) break;
        const GemmJob J = (o == 0) ? j0 : (o == 1) ? j1 : j2;

        float acc[4][8][4];
#pragma unroll
        for (int mi = 0; mi < 4; mi++)
#pragma unroll
            for (int ni = 0; ni < 8; ni++)
#pragma unroll
                for (int r = 0; r < 4; r++) acc[mi][ni][r] = 0.f;

        g_load(0, J.A, J.B);
        s_store(0);
        __syncthreads();

        for (int kt = 0; kt < NKT; kt++) {
            const int cur = kt & 1;
            if (kt + 1 < NKT) g_load(kt + 1, J.A, J.B);

            const uint32_t* asb = &smem[cur * ASZ];
            const uint32_t* bsb = &smem[2 * ASZ + cur * BSZ];
#pragma unroll
            for (int ks = 0; ks < BK; ks += 8) {
                uint32_t a[4][4], b[8][2];
#pragma unroll
                for (int mi = 0; mi < 4; mi++) {
                    int r0 = wm + mi * 16 + qr;
                    a[mi][0] = asb[r0 * LDK + ks + qc];
                    a[mi][1] = asb[(r0 + 8) * LDK + ks + qc];
                    a[mi][2] = asb[r0 * LDK + ks + qc + 4];
                    a[mi][3] = asb[(r0 + 8) * LDK + ks + qc + 4];
                }
#pragma unroll
                for (int ni = 0; ni < 8; ni++) {
                    int c0 = wn + ni * 8 + qr;
                    b[ni][0] = bsb[(ks + qc) * LDBN + c0];
                    b[ni][1] = bsb[(ks + qc + 4) * LDBN + c0];
                }
#pragma unroll
                for (int mi = 0; mi < 4; mi++)
#pragma unroll
                    for (int ni = 0; ni < 8; ni++)
                        mma_tf32(acc[mi][ni], a[mi][0], a[mi][1], a[mi][2], a[mi][3],
                                 b[ni][0], b[ni][1]);
            }

            if (kt + 1 < NKT) {
                s_store(1 - cur);
                __syncthreads();
            }
        }

        if (J.av0) {
            const float* avs[3] = { J.av0, J.av1, J.av2 };
            float*       aos[3] = { J.ao0, J.ao1, J.ao2 };
            const int h0 = wn >> 5;
#pragma unroll
            for (int t = 0; t < 3; t++) {
                const float* av = avs[t];
                if (!av) break;
                float* ao = aos[t];
                float c0[8], c1[8];
#pragma unroll
                for (int ni = 0; ni < 8; ni++) {
                    int col = wn + ni * 8 + qc * 2;
                    int idx = (col >> 5) * 64 + (col & 31);
                    c0[ni] = av[idx];
                    c1[ni] = av[idx + 1];
                }
#pragma unroll
                for (int mi = 0; mi < 4; mi++) {
#pragma unroll
                    for (int half = 0; half < 2; half++) {
                        float pa = 0.f, pb = 0.f;
#pragma unroll
                        for (int ni = 0; ni < 4; ni++)
                            pa += acc[mi][ni][half * 2] * c0[ni]
                                + acc[mi][ni][half * 2 + 1] * c1[ni];
#pragma unroll
                        for (int ni = 4; ni < 8; ni++)
                            pb += acc[mi][ni][half * 2] * c0[ni]
                                + acc[mi][ni][half * 2 + 1] * c1[ni];
                        pa += __shfl_xor_sync(0xffffffffu, pa, 1);
                        pa += __shfl_xor_sync(0xffffffffu, pa, 2);
                        pb += __shfl_xor_sync(0xffffffffu, pb, 1);
                        pb += __shfl_xor_sync(0xffffffffu, pb, 2);
                        int row = m0 + wm + mi * 16 + qr + half * 8;
                        if (qc == 0 && row < M) {
                            ao[row * KH + h0]     = pa;
                            ao[row * KH + h0 + 1] = pb;
                        }
                    }
                }
            }
        }

        float g = 0.f;
        if (J.gate) g = 1.f / (1.f + __expf(-J.gate[0]));

#pragma unroll
        for (int mi = 0; mi < 4; mi++) {
#pragma unroll
            for (int half = 0; half < 2; half++) {
                int row = m0 + wm + mi * 16 + qr + half * 8;
                if (row >= M) continue;
                float* dst = &J.C[(size_t)row * KD + wn];
#pragma unroll
                for (int ni = 0; ni < 8; ni++) {
                    int col = ni * 8 + qc * 2;
                    float2 v;
                    v.x = acc[mi][ni][half * 2 + 0];
                    v.y = acc[mi][ni][half * 2 + 1];
                    if (J.bias) {
                        v.x += J.bias[wn + col + 0];
                        v.y += J.bias[wn + col + 1];
                    }
                    if (J.gate) {
                        float2 prev = *(const float2*)&dst[col];
                        v.x = g * v.x + (1.f - g) * prev.x;
                        v.y = g * v.y + (1.f - g) * prev.y;
                    }
                    *(float2*)&dst[col] = v;
                }
            }
        }
        __syncthreads();
    }
}

// ---------------- CSR build ----------------
__global__ void csr_hist(const int* __restrict__ dst, int* __restrict__ counts)
{
    int e = blockIdx.x * blockDim.x + threadIdx.x;
    if (e < EDG) atomicAdd(&counts[dst[e]], 1);
}

__global__ void scan_block(const int* __restrict__ in, int* __restrict__ out,
                           int* __restrict__ partials, int n)
{
    __shared__ int wsum[8];
    int i = blockIdx.x * 256 + threadIdx.x;
    int lane = threadIdx.x & 31, wid = threadIdx.x >> 5;
    int v = (i < n) ? in[i] : 0;
    int x = v;
#pragma unroll
    for (int o = 1; o < 32; o <<= 1) {
        int t = __shfl_up_sync(0xffffffffu, x, o);
        if (lane >= o) x += t;
    }
    if (lane == 31) wsum[wid] = x;
    __syncthreads();
    if (wid == 0) {
        int w = (lane < 8) ? wsum[lane] : 0;
#pragma unroll
        for (int o = 1; o < 8; o <<= 1) {
            int t = __shfl_up_sync(0xffffffffu, w, o);
            if (lane >= o) w += t;
        }
        if (lane < 8) wsum[lane] = w;
    }
    __syncthreads();
    int wpre = (wid > 0) ? wsum[wid - 1] : 0;
    if (i < n) out[i] = wpre + x - v;
    if (threadIdx.x == 0) partials[blockIdx.x] = wsum[7];
}

__global__ void scan_top(int* __restrict__ partials, int nb)
{
    __shared__ int wsum[8];
    int i = threadIdx.x;
    int lane = i & 31, wid = i >> 5;
    int v = (i < nb) ? partials[i] : 0;
    int x = v;
#pragma unroll
    for (int o = 1; o < 32; o <<= 1) {
        int t = __shfl_up_sync(0xffffffffu, x, o);
        if (lane >= o) x += t;
    }
    if (lane == 31) wsum[wid] = x;
    __syncthreads();
    if (wid == 0) {
        int w = (lane < 8) ? wsum[lane] : 0;
#pragma unroll
        for (int o = 1; o < 8; o <<= 1) {
            int t = __shfl_up_sync(0xffffffffu, w, o);
            if (lane >= o) w += t;
        }
        if (lane < 8) wsum[lane] = w;
    }
    __syncthreads();
    int wpre = (wid > 0) ? wsum[wid - 1] : 0;
    if (i < nb) partials[i] = wpre + x - v;
    if (i == 0) partials[nb] = wsum[7];
}

__global__ void scan_add(int* __restrict__ offsets, const int* __restrict__ partials, int n)
{
    int i = blockIdx.x * 256 + threadIdx.x;
    if (i < n) offsets[i] += partials[blockIdx.x];
    if (i == 0) offsets[n] = partials[gridDim.x];
}

__global__ void csr_scatter(const int* __restrict__ src, const int* __restrict__ dst,
                            const int* __restrict__ offsets, int* __restrict__ cursor,
                            int* __restrict__ ssort)
{
    int e = blockIdx.x * blockDim.x + threadIdx.x;
    if (e >= EDG) return;
    int d = dst[e];
    int pos = offsets[d] + atomicAdd(&cursor[d], 1);
    ssort[pos] = src[e];
}

// ---------------- fused micro gather ----------------
__global__ void micro_gather(const int* __restrict__ ssort, const int* __restrict__ offsets,
                             const float* __restrict__ el, const float* __restrict__ er,
                             const float* __restrict__ Psrc, float* __restrict__ ft, int n_dst)
{
    int d = (blockIdx.x * blockDim.x + threadIdx.x) >> 5;
    int lane = threadIdx.x & 31;
    if (d >= n_dst) return;
    int beg = offsets[d], end = offsets[d + 1];
    float* dstp = &ft[(size_t)d * KD + lane * 8];
    if (beg == end) {
        float4 z = make_float4(0.f, 0.f, 0.f, 0.f);
        *(float4*)dstp = z;
        *(float4*)(dstp + 4) = z;
        return;
    }
    const int h8 = lane & 7;
    float erh = er[d * KH + h8];

    float mx = -1e30f;
    {
        int sub = lane >> 3;
        for (int i = beg; i < end; i += 4) {
            int e = i + sub;
            if (e < end) {
                int s = ssort[e];
                mx = fmaxf(mx, leaky(el[s * KH + h8] + erh));
            }
        }
        mx = fmaxf(mx, __shfl_xor_sync(0xffffffffu, mx, 8));
        mx = fmaxf(mx, __shfl_xor_sync(0xffffffffu, mx, 16));
    }

    const int hk = lane >> 2;
    float acc[8] = {0.f, 0.f, 0.f, 0.f, 0.f, 0.f, 0.f, 0.f};
    float se = 0.f;
    int i = beg;
    for (; i + 2 <= end; i += 2) {
        int s0 = ssort[i], s1 = ssort[i + 1];
        float w0 = 0.f, w1 = 0.f;
        if (lane < KH) {
            w0 = __expf(leaky(el[s0 * KH + lane] + erh) - mx);
            w1 = __expf(leaky(el[s1 * KH + lane] + erh) - mx);
            se += w0 + w1;
        }
        float wk0 = __shfl_sync(0xffffffffu, w0, hk);
        float wk1 = __shfl_sync(0xffffffffu, w1, hk);
        const float4* p0 = (const float4*)&Psrc[(size_t)s0 * KD + lane * 8];
        const float4* p1 = (const float4*)&Psrc[(size_t)s1 * KD + lane * 8];
        float4 a0 = p0[0], a1 = p0[1], b0 = p1[0], b1 = p1[1];
        acc[0] = fmaf(wk0, a0.x, acc[0]); acc[0] = fmaf(wk1, b0.x, acc[0]);
        acc[1] = fmaf(wk0, a0.y, acc[1]); acc[1] = fmaf(wk1, b0.y, acc[1]);
        acc[2] = fmaf(wk0, a0.z, acc[2]); acc[2] = fmaf(wk1, b0.z, acc[2]);
        acc[3] = fmaf(wk0, a0.w, acc[3]); acc[3] = fmaf(wk1, b0.w, acc[3]);
        acc[4] = fmaf(wk0, a1.x, acc[4]); acc[4] = fmaf(wk1, b1.x, acc[4]);
        acc[5] = fmaf(wk0, a1.y, acc[5]); acc[5] = fmaf(wk1, b1.y, acc[5]);
        acc[6] = fmaf(wk0, a1.z, acc[6]); acc[6] = fmaf(wk1, b1.z, acc[6]);
        acc[7] = fmaf(wk0, a1.w, acc[7]); acc[7] = fmaf(wk1, b1.w, acc[7]);
    }
    if (i < end) {
        int s0 = ssort[i];
        float w0 = 0.f;
        if (lane < KH) {
            w0 = __expf(leaky(el[s0 * KH + lane] + erh) - mx);
            se += w0;
        }
        float wk0 = __shfl_sync(0xffffffffu, w0, hk);
        const float4* p0 = (const float4*)&Psrc[(size_t)s0 * KD + lane * 8];
        float4 a0 = p0[0], a1 = p0[1];
        acc[0] = fmaf(wk0, a0.x, acc[0]);
        acc[1] = fmaf(wk0, a0.y, acc[1]);
        acc[2] = fmaf(wk0, a0.z, acc[2]);
        acc[3] = fmaf(wk0, a0.w, acc[3]);
        acc[4] = fmaf(wk0, a1.x, acc[4]);
        acc[5] = fmaf(wk0, a1.y, acc[5]);
        acc[6] = fmaf(wk0, a1.z, acc[6]);
        acc[7] = fmaf(wk0, a1.w, acc[7]);
    }
    float inv = 1.f / __shfl_sync(0xffffffffu, se, hk);
    float4 o0, o1;
    o0.x = fmaxf(acc[0] * inv, 0.f);
    o0.y = fmaxf(acc[1] * inv, 0.f);
    o0.z = fmaxf(acc[2] * inv, 0.f);
    o0.w = fmaxf(acc[3] * inv, 0.f);
    o1.x = fmaxf(acc[4] * inv, 0.f);
    o1.y = fmaxf(acc[5] * inv, 0.f);
    o1.z = fmaxf(acc[6] * inv, 0.f);
    o1.w = fmaxf(acc[7] * inv, 0.f);
    *(float4*)dstp = o0;
    *(float4*)(dstp + 4) = o1;
}

// ---------------- final paper ----------------
__global__ void final_paper(const float* __restrict__ rfw, const float* __restrict__ rfc,
                            const float* __restrict__ nodep, const float* __restrict__ attnM,
                            const float* __restrict__ resw, float* __restrict__ out)
{
    int n = blockIdx.x;
    int k = threadIdx.x >> 5;
    int lane = threadIdx.x & 31;
    size_t idx = (size_t)n * KD + k * DH + lane;
    float np = nodep[idx], rw = rfw[idx], rc = rfc[idx];
    float a1 = attnM[k * 64 + lane];
    float a2 = attnM[k * 64 + 32 + lane];
    float sw = a1 * np + a2 * rw;
    float sc = a1 * np + a2 * rc;
#pragma unroll
    for (int s = 16; s > 0; s >>= 1) {
        sw += __shfl_xor_sync(0xffffffffu, sw, s);
        sc += __shfl_xor_sync(0xffffffffu, sc, s);
    }
    sw = leaky(sw);
    sc = leaky(sc);
    float mx = fmaxf(sw, sc);
    float ew = __expf(sw - mx), ec = __expf(sc - mx);
    float aw = ew / (ew + ec);
    float val = aw * rw + (1.f - aw) * rc;
    float g = 1.f / (1.f + __expf(-resw[0]));
    size_t o = (size_t)NA * KD + idx;
    out[o] = g * val + (1.f - g) * out[o];
}

// ---------------- launch ----------------
extern "C" void kernel_launch(void* const* d_in, const int* in_sizes, int n_in,
                              void* d_out, int out_size)
{
    const float* feats_author    = (const float*)d_in[0];
    const float* feats_paper     = (const float*)d_in[1];
    const float* W_micro_author  = (const float*)d_in[2];
    const float* W_micro_paper   = (const float*)d_in[3];
    const float* attn_micro_a    = (const float*)d_in[4];
    const float* attn_micro_p    = (const float*)d_in[5];
    const float* W_macro_node_p  = (const float*)d_in[7];
    const float* W_rel_writes    = (const float*)d_in[8];
    const float* W_rel_wb        = (const float*)d_in[9];
    const float* W_rel_cites     = (const float*)d_in[10];
    const float* attn_macro      = (const float*)d_in[11];
    const float* W_res_author    = (const float*)d_in[12];
    const float* b_res_author    = (const float*)d_in[13];
    const float* W_res_paper     = (const float*)d_in[14];
    const float* b_res_paper     = (const float*)d_in[15];
    const float* res_w_author    = (const float*)d_in[16];
    const float* res_w_paper     = (const float*)d_in[17];
    const int*   writes_src      = (const int*)d_in[18];
    const int*   writes_dst      = (const int*)d_in[19];
    const int*   wb_src          = (const int*)d_in[20];
    const int*   wb_dst          = (const int*)d_in[21];
    const int*   cites_src       = (const int*)d_in[22];
    const int*   cites_dst       = (const int*)d_in[23];
    float* out = (float*)d_out;

    float *PA, *PP, *elA_aA, *erP_aA, *elP_aP, *erA_aP, *erP_aP;
    float *ft_w, *ft_wb, *ft_c, *rf_w, *rf_c, *nodeP;
    int *counts, *cursor, *offsets, *partials, *ssort;
    cudaGetSymbolAddress((void**)&PA, g_PA);
    cudaGetSymbolAddress((void**)&PP, g_PP);
    cudaGetSymbolAddress((void**)&elA_aA, g_elA_aA);
    cudaGetSymbolAddress((void**)&erP_aA, g_erP_aA);
    cudaGetSymbolAddress((void**)&elP_aP, g_elP_aP);
    cudaGetSymbolAddress((void**)&erA_aP, g_erA_aP);
    cudaGetSymbolAddress((void**)&erP_aP, g_erP_aP);
    cudaGetSymbolAddress((void**)&ft_w, g_ft_w);
    cudaGetSymbolAddress((void**)&ft_wb, g_ft_wb);
    cudaGetSymbolAddress((void**)&ft_c, g_ft_c);
    cudaGetSymbolAddress((void**)&rf_w, g_rf_w);
    cudaGetSymbolAddress((void**)&rf_c, g_rf_c);
    cudaGetSymbolAddress((void**)&nodeP, g_nodeP);
    cudaGetSymbolAddress((void**)&counts, g_counts);
    cudaGetSymbolAddress((void**)&cursor, g_cursor);
    cudaGetSymbolAddress((void**)&offsets, g_offsets);
    cudaGetSymbolAddress((void**)&partials, g_partials);
    cudaGetSymbolAddress((void**)&ssort, g_ssort);

    static cudaStream_t s2 = nullptr;
    static cudaEvent_t evFork = nullptr, evA = nullptr, evG0 = nullptr,
                       evG2 = nullptr, evS2 = nullptr;
    if (!s2) {
        cudaStreamCreateWithFlags(&s2, cudaStreamNonBlocking);
        cudaEventCreateWithFlags(&evFork, cudaEventDisableTiming);
        cudaEventCreateWithFlags(&evA, cudaEventDisableTiming);
        cudaEventCreateWithFlags(&evG0, cudaEventDisableTiming);
        cudaEventCreateWithFlags(&evG2, cudaEventDisableTiming);
        cudaEventCreateWithFlags(&evS2, cudaEventDisableTiming);
    }

    cudaFuncSetAttribute(gemm_multi, cudaFuncAttributeMaxDynamicSharedMemorySize, SMEM_BYTES);

    const int GG = (NA + BM - 1) / BM;          // 391
    const int EB = (EDG + 255) / 256;
    const int GB = (NA * 32 + 255) / 256;

    GemmJob jz = {};

    struct Rel { const int* src; const int* dst; };
    Rel rels[3] = {
        { writes_src, writes_dst },
        { wb_src,     wb_dst     },
        { cites_src,  cites_dst  },
    };

    // ---- fork: s2 runs CSR builds for all 3 relations ----
    cudaEventRecord(evFork, 0);
    cudaStreamWaitEvent(s2, evFork, 0);
    for (int r = 0; r < 3; r++) {
        Rel& R = rels[r];
        int* cnt = counts  + r * 50000;
        int* cur = cursor  + r * 50000;
        int* off = offsets + r * 50001;
        int* par = partials + r * (NBLK + 1);
        int* srt = ssort   + r * EDG;
        cudaMemsetAsync(cnt, 0, 50000 * sizeof(int), s2);
        cudaMemsetAsync(cur, 0, 50000 * sizeof(int), s2);
        csr_hist<<<EB, 256, 0, s2>>>(R.dst, cnt);
        scan_block<<<NBLK, 256, 0, s2>>>(cnt, off, par, 50000);
        scan_top<<<1, 256, 0, s2>>>(par, NBLK);
        scan_add<<<NBLK, 256, 0, s2>>>(off, par, 50000);
        csr_scatter<<<EB, 256, 0, s2>>>(R.src, R.dst, off, cur, srt);
    }

    // ---- main: author micro GEMM (+fused attn dots) ----
    {
        GemmJob ja = { feats_author, W_micro_author, PA, nullptr, nullptr,
                       attn_micro_a + 0,  elA_aA,
                       attn_micro_p + 32, erA_aP,
                       nullptr, nullptr };
        gemm_multi<<<GG, 256, SMEM_BYTES>>>(ja, jz, jz, 1, NA);
    }
    cudaEventRecord(evA, 0);

    // ---- s2: paper micro GEMM (+3 fused attn dots), concurrent with main ----
    {
        GemmJob ja = { feats_paper, W_micro_paper, PP, nullptr, nullptr,
                       attn_micro_a + 32, erP_aA,
                       attn_micro_p + 0,  elP_aP,
                       attn_micro_p + 32, erP_aP };
        gemm_multi<<<GG, 256, SMEM_BYTES, s2>>>(ja, jz, jz, 1, NP);
    }

    // ---- s2: gather cites (paper-only deps) immediately ----
    micro_gather<<<GB, 256, 0, s2>>>(ssort + 2 * EDG, offsets + 2 * 50001,
                                     elP_aP, erP_aP, PP, ft_c, NP);
    cudaEventRecord(evG2, s2);

    // ---- s2: remaining gathers need author micro ----
    cudaStreamWaitEvent(s2, evA, 0);
    micro_gather<<<GB, 256, 0, s2>>>(ssort + 0 * EDG, offsets + 0 * 50001,
                                     elA_aA, erP_aA, PA, ft_w, NP);
    cudaEventRecord(evG0, s2);
    micro_gather<<<GB, 256, 0, s2>>>(ssort + 1 * EDG, offsets + 1 * 50001,
                                     elP_aP, erA_aP, PP, ft_wb, NA);

    // ---- s2: gated wb macro GEMM (writes out[:NA]); after res_author exists ----
    // (wb GEMM reads out[:NA] as prev — must wait for the main-stream 3-job GEMM)

    // ---- main: 3-job GEMM (res_author -> out[:NA], nodeP, res_paper -> out[NA:]) ----
    {
        GemmJob ja = { feats_author, W_res_author, out, b_res_author, nullptr,
                       nullptr, nullptr, nullptr, nullptr, nullptr, nullptr };
        GemmJob jb = { feats_paper, W_macro_node_p, nodeP, nullptr, nullptr,
                       nullptr, nullptr, nullptr, nullptr, nullptr, nullptr };
        GemmJob jc = { feats_paper, W_res_paper, out + (size_t)NA * KD, b_res_paper, nullptr,
                       nullptr, nullptr, nullptr, nullptr, nullptr, nullptr };
        gemm_multi<<<GG, 256, SMEM_BYTES>>>(ja, jb, jc, 3, NA);
    }
    static cudaEvent_t evRes = nullptr;
    if (!evRes) cudaEventCreateWithFlags(&evRes, cudaEventDisableTiming);
    cudaEventRecord(evRes, 0);

    // s2: wb gated GEMM (needs ft_wb in-stream; needs out[:NA] residual from main)
    cudaStreamWaitEvent(s2, evRes, 0);
    {
        GemmJob ja = { ft_wb, W_rel_wb, out, nullptr, res_w_author,
                       nullptr, nullptr, nullptr, nullptr, nullptr, nullptr };
        gemm_multi<<<GG, 256, SMEM_BYTES, s2>>>(ja, jz, jz, 1, NA);
    }
    cudaEventRecord(evS2, s2);

    // ---- main: rf_w and rf_c macro GEMMs, concurrent with s2's wb GEMM ----
    cudaStreamWaitEvent(0, evG0, 0);
    {
        GemmJob ja = { ft_w, W_rel_writes, rf_w, nullptr, nullptr,
                       nullptr, nullptr, nullptr, nullptr, nullptr, nullptr };
        gemm_multi<<<GG, 256, SMEM_BYTES>>>(ja, jz, jz, 1, NP);
    }
    cudaStreamWaitEvent(0, evG2, 0);
    {
        GemmJob ja = { ft_c, W_rel_cites, rf_c, nullptr, nullptr,
                       nullptr, nullptr, nullptr, nullptr, nullptr, nullptr };
        gemm_multi<<<GG, 256, SMEM_BYTES>>>(ja, jz, jz, 1, NP);
    }

    // ---- join s2, then final paper fusion ----
    cudaStreamWaitEvent(0, evS2, 0);
    final_paper<<<NP, 256>>>(rf_w, rf_c, nodeP, attn_macro, res_w_paper, out);
}